// round 16
// baseline (speedup 1.0000x reference)
#include <cuda_runtime.h>

#define NN 2048
#define EE 16384
#define DIN 1280
#define MAXDEG 64          // fixed-stride CSR slot capacity

// -------- device scratch (no allocation allowed) --------
__device__ float   g_h[NN];               // h = x_orig @ W2^T
__device__ int     g_deg[NN];             // in-degree counters
__device__ float4  g_edge[NN * MAXDEG];   // {src_bits, w, w*h_src, 0} per in-edge of dst
__device__ float2  g_self[NN];            // {self_w, self_w * h_i}

// ------- k_h: h = x_orig @ W2^T, 2 rows/block, 4 warps/row, W2 staged in smem -------
__global__ void __launch_bounds__(256) k_h(const float* __restrict__ xo,
                    const float* __restrict__ W2,
                    const float* __restrict__ att_src, const float* __restrict__ att_dst) {
    __shared__ float4 w2s[DIN / 4];        // 320 float4 = 5KB
    __shared__ float partial[8];
    const int tid = threadIdx.x, wp = tid >> 5, lane = tid & 31;

    // cooperative W2 stage (one 5KB load per block instead of per-thread dup)
    const float4* wr = (const float4*)W2;
    for (int i = tid; i < DIN / 4; i += 256) w2s[i] = wr[i];
    __syncthreads();

    const int row = blockIdx.x * 2 + (wp >> 2);
    const int b0 = (wp & 3) * 80;                       // 320 float4 per row / 4 warps
    const float4* xr = (const float4*)(xo + (size_t)row * DIN);

    float acc;
    {
        float4 a = xr[b0 + lane],      b = w2s[b0 + lane];
        acc = a.x * b.x + a.y * b.y + a.z * b.z + a.w * b.w;
        a = xr[b0 + 32 + lane];        b = w2s[b0 + 32 + lane];
        acc += a.x * b.x + a.y * b.y + a.z * b.z + a.w * b.w;
        if (lane < 16) {
            a = xr[b0 + 64 + lane];    b = w2s[b0 + 64 + lane];
            acc += a.x * b.x + a.y * b.y + a.z * b.z + a.w * b.w;
        }
    }
#pragma unroll
    for (int off = 16; off; off >>= 1) acc += __shfl_xor_sync(0xffffffffu, acc, off);
    if (lane == 0) partial[wp] = acc;
    __syncthreads();
    if (tid < 2) {
        int r = blockIdx.x * 2 + tid;
        float h = partial[tid * 4] + partial[tid * 4 + 1]
                + partial[tid * 4 + 2] + partial[tid * 4 + 3];
        g_h[r] = h;
        g_deg[r] = 0;
        float z = (att_src[0] + att_dst[0]) * h;        // self-loop logit
        float self = z > 0.f ? z : 0.2f * z;
        float sw = __expf(self);                         // unshifted (validated)
        g_self[r] = make_float2(sw, sw * h);
    }
}

// ------- k_scatter: CSR scatter + per-edge exp weight (shift-free) -------
__global__ void k_scatter(const int* __restrict__ ei,
                          const float* __restrict__ att_src,
                          const float* __restrict__ att_dst) {
    int e = blockIdx.x * blockDim.x + threadIdx.x;
    if (e < EE) {
        int s = ei[e];
        int d = ei[EE + e];
        float hs = g_h[s], hd = g_h[d];
        float z = att_src[0] * hs + att_dst[0] * hd;
        float l = z > 0.f ? z : 0.2f * z;                // leaky-relu(0.2)
        float w = __expf(l);
        int p = atomicAdd(&g_deg[d], 1);
        if (p < MAXDEG) {
            g_edge[d * MAXDEG + p] = make_float4(__int_as_float(s), w, w * hs, 0.f);
        }
    }
}

// GAT value for node i inside ego mask `row`
__device__ __forceinline__ float ego_e(int i, const unsigned* row, float bi) {
    float2 sf = g_self[i];
    float denom = sf.x, num = sf.y;
    int di = min(g_deg[i], MAXDEG);
    const float4* ep = g_edge + i * MAXDEG;
#pragma unroll 4
    for (int j = 0; j < di; j++) {
        float4 pk = ep[j];
        int s = __float_as_int(pk.x);
        if ((row[s >> 5] >> (s & 31)) & 1u) { denom += pk.y; num += pk.z; }
    }
    return __expf(num / denom + bi);
}

// ------- k_ego: 128-thr block/ego — zero rows, mask, bit-owned GAT, scatter -------
// smem ~800B, 16 blocks/SM -> 2048 blocks in ~0.87 waves, 4 barriers total
__global__ void __launch_bounds__(128) k_ego(const float* __restrict__ bias,
                                             float* __restrict__ out, int write_mask) {
    __shared__ unsigned row[64];
    __shared__ int s1[MAXDEG];
    __shared__ int s1d[MAXDEG];
    __shared__ float red[4];
    const int v = blockIdx.x;
    const int tid = threadIdx.x, lane = tid & 31, wp = tid >> 5;
    const float bi = bias[0];

    float* so = out + (size_t)v * NN;
    float* mo = out + (size_t)NN * NN + (size_t)v * NN;

    // ---- 0: zero this ego's output rows FIRST (stores drain under later loads) ----
    {
        float4 z4 = make_float4(0.f, 0.f, 0.f, 0.f);
        float4* so4 = (float4*)so;
        float4* mo4 = (float4*)mo;
#pragma unroll
        for (int t = tid; t < NN / 4; t += 128) {
            so4[t] = z4;
            if (write_mask) mo4[t] = z4;
        }
    }
    if (tid < 64) row[tid] = 0u;
    __syncthreads();

    // ---- 1: 1-hop into shared ----
    const int dv = min(g_deg[v], MAXDEG);
    if (tid == 0) atomicOr(&row[v >> 5], 1u << (v & 31));
    const float* ex = (const float*)g_edge;              // .x at stride 4
    for (int k = tid; k < dv; k += 128) {
        int s = __float_as_int(__ldg(&ex[(v * MAXDEG + k) * 4]));
        s1[k] = s;
        s1d[k] = min(g_deg[s], MAXDEG);
        atomicOr(&row[s >> 5], 1u << (s & 31));
    }
    __syncthreads();

    // ---- 2: 2-hop, flat (k, j) parallel — all loads independent ----
    const int tot = dv * MAXDEG;
    for (int t = tid; t < tot; t += 128) {
        int k = t >> 6, j = t & 63;
        if (j < s1d[k]) {
            int s = s1[k];
            int u = __float_as_int(__ldg(&ex[(s * MAXDEG + j) * 4]));
            atomicOr(&row[u >> 5], 1u << (u & 31));
        }
    }
    __syncthreads();

    // ---- 3: GAT + exp; thread tid owns 16 bits of word (tid>>1) ----
    const int wrd = tid >> 1, hi16 = tid & 1;
    const int base = wrd * 32 + hi16 * 16;
    const unsigned mybits = (row[wrd] >> (hi16 * 16)) & 0xffffu;
    float evloc[4];
    float sm = 0.f;
    {
        unsigned m = mybits;
        int nb = 0;
        while (m) {
            int b = __ffs(m) - 1;
            m &= m - 1;
            int i = base + b;
            float e = ego_e(i, row, bi);
            if (nb < 4) evloc[nb] = e;
            else        so[i] = e;                       // rare spill, rescaled below
            nb++;
            sm += e;
        }
    }
#pragma unroll
    for (int off = 16; off; off >>= 1) sm += __shfl_xor_sync(0xffffffffu, sm, off);
    if (lane == 0) red[wp] = sm;
    __syncthreads();                                     // also orders zero-stores
    const float inv = 1.f / (red[0] + red[1] + red[2] + red[3]);

    // ---- 4: scaled sparse scatter + mask bits ----
    {
        unsigned m = mybits;
        int nb = 0;
        while (m) {
            int b = __ffs(m) - 1;
            m &= m - 1;
            int i = base + b;
            float e = (nb < 4) ? evloc[nb] : so[i];      // same-thread reload, ordered
            so[i] = e * inv;
            if (write_mask) mo[i] = 1.f;
            nb++;
        }
    }
}

// ---------------- launch ----------------
extern "C" void kernel_launch(void* const* d_in, const int* in_sizes, int n_in,
                              void* d_out, int out_size) {
    // inputs: 0:x 1:x_orig 2:edge_index 3:batch 4:W2 5:att_src 6:att_dst 7:bias
    const float* x_orig  = (const float*)d_in[1];
    const int*   ei      = (const int*)d_in[2];
    const float* W2      = (const float*)d_in[4];
    const float* att_src = (const float*)d_in[5];
    const float* att_dst = (const float*)d_in[6];
    const float* bias    = (const float*)d_in[7];
    float* out = (float*)d_out;
    int write_mask = (out_size >= 2 * NN * NN) ? 1 : 0;

    k_h<<<NN / 2, 256>>>(x_orig, W2, att_src, att_dst);
    k_scatter<<<EE / 256, 256>>>(ei, att_src, att_dst);
    k_ego<<<NN, 128>>>(bias, out, write_mask);
}